// round 15
// baseline (speedup 1.0000x reference)
#include <cuda_runtime.h>
#include <math.h>

#define T_STEPS 256
typedef unsigned long long u64t;

struct Sc {
    float D22[32 * 32];
    float vr[160 * 32];
    float T1[160 * 32];
    float H[160 * 160];
};
__device__ Sc g_s;

// Weight image: WA 3072 | WX 8192 | WYF 4096 | DC 1024 = 16384 floats (64 KB)
#define OFF_WA 0
#define OFF_WX 3072
#define OFF_WY 11264
#define OFF_DC 15360
__device__ __align__(16) float g_params[16384];

__device__ __forceinline__ u64t f2_fma(u64t a, u64t b, u64t c) {
    u64t d; asm("fma.rn.f32x2 %0,%1,%2,%3;" : "=l"(d) : "l"(a), "l"(b), "l"(c)); return d;
}
__device__ __forceinline__ float f2_fold(u64t v) {
    float lo, hi; asm("mov.b64 {%0,%1},%2;" : "=f"(lo), "=f"(hi) : "l"(v));
    return lo + hi;
}
// tanh via ex2+rcp (abs err ~1e-7)
__device__ __forceinline__ float tanh_fast(float x) {
    float t = x * 2.885390081777926814f;
    float e; asm("ex2.approx.f32 %0,%1;" : "=f"(e) : "f"(t));
    float r; asm("rcp.approx.f32 %0,%1;" : "=f"(r) : "f"(e + 1.0f));
    return fmaf(-2.0f, r, 1.0f);
}

// ---------------- Gauss-Jordan (fp32, warp-parallel partial pivot) ----------------
__device__ void gj_invert_f32(float* aug, int N, float* mv, int* s_piv, float* s_ipv) {
    const int tid = threadIdx.x, NT = blockDim.x;
    const int ld = 2 * N;
    for (int k = 0; k < N; k++) {
        if (tid < 32) {
            float best = -1.0f; int bi = k;
            for (int r = k + tid; r < N; r += 32) {
                float v = fabsf(aug[r * ld + k]);
                if (v > best) { best = v; bi = r; }
            }
            for (int o = 16; o; o >>= 1) {
                float ob = __shfl_down_sync(0xffffffffu, best, o);
                int   oi = __shfl_down_sync(0xffffffffu, bi, o);
                if (ob > best) { best = ob; bi = oi; }
            }
            if (tid == 0) *s_piv = bi;
        }
        __syncthreads();
        int p = *s_piv;
        if (p != k)
            for (int j = tid; j < ld; j += NT) {
                float tv = aug[k * ld + j];
                aug[k * ld + j] = aug[p * ld + j];
                aug[p * ld + j] = tv;
            }
        __syncthreads();
        if (tid == 0) *s_ipv = 1.0f / aug[k * ld + k];
        __syncthreads();
        float ipv = *s_ipv;
        for (int j = tid; j < ld; j += NT) aug[k * ld + j] *= ipv;
        __syncthreads();
        for (int r = tid; r < N; r += NT) mv[r] = aug[r * ld + k];
        __syncthreads();
        for (int idx = tid; idx < N * ld; idx += NT) {
            int r = idx / ld;
            if (r != k) {
                int j = idx - r * ld;
                aug[idx] -= mv[r] * aug[k * ld + j];
            }
        }
        __syncthreads();
    }
}

// ---------------- Setup A (1 block x 256) — ALL-SMEM (R14 verbatim) ----------------
__global__ void ren_setup_a(const float* __restrict__ B2, const float* __restrict__ C2,
                            const float* __restrict__ D12, const float* __restrict__ L,
                            const float* __restrict__ U, const float* __restrict__ D21,
                            const float* __restrict__ gamma) {
    extern __shared__ float sf[];
    float* sL    = sf;
    float* sU    = sf + 1024;
    float* sC2   = sf + 2048;
    float* sD12  = sf + 4096;
    float* sD21  = sf + 5120;
    float* sB2   = sf + 6144;
    float* sD22  = sf + 8192;
    float* sM    = sf + 9216;
    float* aug   = sf + 10240;
    float* sRinv = sf + 12288;
    float* svr   = sf + 13312;
    float* mv    = sf + 18432;
    __shared__ int s_piv;
    __shared__ float s_ipv;
    const int tid = threadIdx.x, NT = blockDim.x;
    const float g = gamma[0];

    for (int i = tid; i < 1024; i += NT) sL[i]   = L[i];
    for (int i = tid; i < 1024; i += NT) sU[i]   = U[i];
    for (int i = tid; i < 2048; i += NT) sC2[i]  = C2[i];
    for (int i = tid; i < 1024; i += NT) sD12[i] = D12[i];
    for (int i = tid; i < 1024; i += NT) sD21[i] = D21[i];
    for (int i = tid; i < 2048; i += NT) sB2[i]  = B2[i];
    __syncthreads();

    for (int idx = tid; idx < 1024; idx += NT) {
        int i = idx >> 5, j = idx & 31;
        float acc = (i == j) ? (g + 1.0f) : 0.0f;
        #pragma unroll 8
        for (int k = 0; k < 32; k++) acc += sL[k * 32 + i] * sL[k * 32 + j];
        acc += sU[i * 32 + j] - sU[j * 32 + i];
        sD22[idx] = acc;
        g_s.D22[idx] = acc;
    }
    __syncthreads();

    for (int idx = tid; idx < 2048; idx += NT) {
        int i = idx >> 6, j = idx & 63;
        float v;
        if (j < 32) {
            float s = 0.0f;
            #pragma unroll 8
            for (int k = 0; k < 32; k++) s += sD22[k * 32 + i] * sD22[k * 32 + j];
            v = sD22[i * 32 + j] + sD22[j * 32 + i] - 1e-4f * s;
            if (i == j) v += -2.0f * g;
        } else v = ((j - 32) == i) ? 1.0f : 0.0f;
        aug[idx] = v;
    }
    __syncthreads();
    gj_invert_f32(aug, 32, mv, &s_piv, &s_ipv);
    for (int idx = tid; idx < 1024; idx += NT) {
        int i = idx >> 5, j = idx & 31;
        sRinv[idx] = aug[i * 64 + 32 + j];
    }
    for (int idx = tid; idx < 1024; idx += NT) {
        int i = idx >> 5, j = idx & 31;
        sM[idx] = ((i == j) ? 1.0f : 0.0f) - 1e-4f * sD22[j * 32 + i];
    }
    __syncthreads();

    for (int idx = tid; idx < 160 * 32; idx += NT) {
        int r = idx >> 5, c = idx & 31;
        float v;
        if (r < 64) {
            float s = 0.0f;
            #pragma unroll 8
            for (int k = 0; k < 32; k++) s += sM[c * 32 + k] * sC2[k * 64 + r];
            v = s;
        } else if (r < 96) {
            int rr = r - 64;
            float s = 0.0f;
            #pragma unroll 8
            for (int k = 0; k < 32; k++) s += sM[c * 32 + k] * sD21[k * 32 + rr];
            v = s - sD12[rr * 32 + c];
        } else v = sB2[(r - 96) * 32 + c];
        svr[idx] = v;
        g_s.vr[idx] = v;
    }
    __syncthreads();

    for (int idx = tid; idx < 160 * 32; idx += NT) {
        int r = idx >> 5, c = idx & 31;
        float s = 0.0f;
        #pragma unroll 8
        for (int k = 0; k < 32; k++) s += svr[r * 32 + k] * sRinv[k * 32 + c];
        g_s.T1[idx] = s;
    }
}

// ---------------- Setup B (160 blocks, R14 verbatim) ----------------
__global__ void ren_setup_b(const float* __restrict__ X, const float* __restrict__ C2,
                            const float* __restrict__ D21) {
    __shared__ float Xa[160];
    __shared__ float T1a[32];
    __shared__ float vqa[32];
    const int a = blockIdx.x;
    const int tid = threadIdx.x;
    for (int k = tid; k < 160; k += blockDim.x) Xa[k] = X[k * 160 + a];
    if (tid < 32) {
        T1a[tid] = g_s.T1[a * 32 + tid];
        float vq = 0.0f;
        if (a < 64) vq = C2[tid * 64 + a];
        else if (a < 96) vq = D21[tid * 32 + (a - 64)];
        vqa[tid] = vq;
    }
    __syncthreads();
    for (int b = tid; b < 160; b += blockDim.x) {
        float gsum = 0.0f;
        for (int k = 0; k < 160; k++) gsum += Xa[k] * X[k * 160 + b];
        float pr = 0.0f;
        for (int c = 0; c < 32; c++) pr += T1a[c] * g_s.vr[b * 32 + c];
        float q = 0.0f;
        if (b < 96)
            for (int c = 0; c < 32; c++) {
                float vb = (b < 64) ? C2[c * 64 + b] : D21[c * 32 + (b - 64)];
                q += vqa[c] * vb;
            }
        float h = gsum + pr + 1e-4f * q;
        if (a == b) h += 1e-3f;
        g_s.H[a * 160 + b] = h;
    }
}

// ---------------- Setup CD (32 blocks x 512, R14 verbatim) ----------------
__global__ void ren_setup_cd(const float* __restrict__ Y, const float* __restrict__ B2,
                             const float* __restrict__ C2, const float* __restrict__ D12,
                             const float* __restrict__ D21) {
    extern __shared__ float sf[];
    float* aug = sf;
    float* mv  = sf + 64 * 128;
    __shared__ int s_piv;
    __shared__ float s_ipv;
    __shared__ float CE[32 * 64];
    const int tid = threadIdx.x, NT = blockDim.x;

    for (int idx = tid; idx < 64 * 128; idx += NT) {
        int i = idx >> 7, j = idx & 127;
        float v;
        if (j < 64)
            v = 0.5f * (g_s.H[i * 160 + j] + g_s.H[(96 + i) * 160 + (96 + j)]
                        + Y[i * 64 + j] - Y[j * 64 + i]);
        else v = ((j - 64) == i) ? 1.0f : 0.0f;
        aug[idx] = v;
    }
    __syncthreads();
    gj_invert_f32(aug, 64, mv, &s_piv, &s_ipv);

#define EINV(r, c) (aug[(r) * 128 + 64 + (c)])
    for (int idx = tid; idx < 32 * 64; idx += NT) {
        int i = idx >> 6, n = idx & 63;
        float s = 0.0f;
        for (int m = 0; m < 64; m++) s += C2[i * 64 + m] * EINV(m, n);
        CE[idx] = s;
    }
    __syncthreads();

    const int g = blockIdx.x * 512 + tid;
    if (g < 8192) {
        int e = g;
        int comp = e & 3, r = e >> 2, j = r >> 5, lane = r & 31;
        int row = (comp < 2) ? lane : lane + 32;
        int c = comp & 1;
        float s = 0.0f;
        if (j < 16) {
            int col = 2 * j + c;
            for (int m = 0; m < 64; m++) s += EINV(row, m) * B2[m * 32 + col];
        } else if (j < 32) {
            int col = 2 * (j - 16) + c;
            for (int m = 0; m < 64; m++) s += EINV(row, m) * g_s.H[(96 + m) * 160 + 64 + col];
        } else {
            int col = 2 * (j - 32) + c;
            for (int m = 0; m < 64; m++) s += EINV(row, m) * g_s.H[(96 + m) * 160 + col];
        }
        g_params[OFF_WX + e] = s;
    } else if (g < 11264) {
        int e = g - 8192;
        int c = e & 1, r = e >> 1, j = r >> 5, i = r & 31;
        float invLam = 1.0f / (0.5f * g_s.H[(64 + i) * 160 + (64 + i)]);
        float v;
        if (j < 16) v = D12[i * 32 + 2 * j + c];
        else        v = -g_s.H[(64 + i) * 160 + 2 * (j - 16) + c];
        g_params[OFF_WA + e] = v * invLam;
    } else if (g < 15360) {
        int e = g - 11264;
        int c = e & 1, r = e >> 1, j = r >> 5, i = r & 31;
        int col;
        float val;
        if (j < 16)      { col = 2 * j + c;        val = g_s.D22[i * 32 + col]; }
        else if (j < 32) { col = 2 * (j - 16) + c; val = D21[i * 32 + col]; }
        else             { col = 2 * (j - 32) + c; val = 0.0f; }
        float acc = 0.0f;
        for (int n = 0; n < 64; n++) {
            float sv;
            if (j < 16)      sv = B2[n * 32 + col];
            else if (j < 32) sv = g_s.H[(96 + n) * 160 + 64 + col];
            else             sv = g_s.H[(96 + n) * 160 + col];
            acc += CE[i * 64 + n] * sv;
        }
        g_params[OFF_WY + e] = val + acc;
    } else {
        int e = g - 15360;
        int i = e >> 5, l = e & 31;
        float invLam = 1.0f / (0.5f * g_s.H[(64 + l) * 160 + (64 + l)]);
        g_params[OFF_DC + e] =
            (l > i) ? (-g_s.H[(64 + l) * 160 + (64 + i)] * invLam) : 0.0f;
    }
#undef EINV
}

// ---------------------------------------------------------------------------
// Main: E=4 per warp, 8 warps/block (2/SMSP), 64 blocks. MATXY fold (R10) +
// wa_r/dc_r register cache. Weight LDS per element HALVED vs R12/R14.
// State per warp: SA float4[96] (elems 0,1), SB float4[96] (elems 2,3).
// ---------------------------------------------------------------------------
__global__ void __launch_bounds__(256, 1)
ren_main(const float* __restrict__ u_in, const float* __restrict__ x0,
         float* __restrict__ y_out) {
    extern __shared__ float sm[];
    {
        float4* dst = (float4*)sm;
        const float4* src = (const float4*)g_params;
        for (int i = threadIdx.x; i < 4096; i += blockDim.x) dst[i] = src[i];
    }
    const int warp = threadIdx.x >> 5;
    const int lane = threadIdx.x & 31;
    float* fS = sm + 16384 + warp * 768;
    const float4* SA = (const float4*)fS;
    const float4* SB = SA + 96;
    __syncthreads();

    // register-cached weights
    u64t wa_r[48];
    #pragma unroll
    for (int j = 0; j < 48; j++)
        wa_r[j] = *(const u64t*)(sm + OFF_WA + (j * 32 + lane) * 2);
    float dc_r[32];
    #pragma unroll
    for (int i = 0; i < 32; i++)
        dc_r[i] = sm[OFF_DC + i * 32 + lane];

    const int e0 = (blockIdx.x * 8 + warp) * 4;
    const float* up0 = u_in + (size_t)(e0 + 0) * (T_STEPS * 32);
    const float* up1 = u_in + (size_t)(e0 + 1) * (T_STEPS * 32);
    const float* up2 = u_in + (size_t)(e0 + 2) * (T_STEPS * 32);
    const float* up3 = u_in + (size_t)(e0 + 3) * (T_STEPS * 32);
    float* yp0 = y_out + (size_t)(e0 + 0) * (T_STEPS * 32) + lane;
    float* yp1 = y_out + (size_t)(e0 + 1) * (T_STEPS * 32) + lane;
    float* yp2 = y_out + (size_t)(e0 + 2) * (T_STEPS * 32) + lane;
    float* yp3 = y_out + (size_t)(e0 + 3) * (T_STEPS * 32) + lane;

    // init x state (kp 64..95), both element pairs
    {
        int ia = (64 + (lane >> 1)) * 4 + (lane & 1);
        int ib = (80 + (lane >> 1)) * 4 + (lane & 1);
        fS[ia]           = x0[(e0 + 0) * 64 + lane];
        fS[ia + 2]       = x0[(e0 + 1) * 64 + lane];
        fS[384 + ia]     = x0[(e0 + 2) * 64 + lane];
        fS[384 + ia + 2] = x0[(e0 + 3) * 64 + lane];
        fS[ib]           = x0[(e0 + 0) * 64 + 32 + lane];
        fS[ib + 2]       = x0[(e0 + 1) * 64 + 32 + lane];
        fS[384 + ib]     = x0[(e0 + 2) * 64 + 32 + lane];
        fS[384 + ib + 2] = x0[(e0 + 3) * 64 + 32 + lane];
    }
    float uc0 = up0[lane], uc1 = up1[lane], uc2 = up2[lane], uc3 = up3[lane];

    const int idxu = (32 + (lane >> 1)) * 4 + (lane & 1);
    const int idxw = (48 + (lane >> 1)) * 4 + (lane & 1);
    const int idxa = (64 + (lane >> 1)) * 4 + (lane & 1);
    const int idxb = (80 + (lane >> 1)) * 4 + (lane & 1);

#define LD2(p)  (*(const ulonglong2*)(p))
// a-phase state map: j<16 -> u at kp 32+j; j>=16 -> x at kp 48+j (=64..95)
#define MATA(kp, j) { \
    ulonglong2 sa = LD2(SA + (kp)); ulonglong2 sb = LD2(SB + (kp)); \
    av0 = f2_fma(wa_r[j], sa.x, av0); av1 = f2_fma(wa_r[j], sa.y, av1); \
    av2 = f2_fma(wa_r[j], sb.x, av2); av3 = f2_fma(wa_r[j], sb.y, av3); }
// combined x+y op for 4 elements: one weight fetch serves all
#define MATXY(j) { \
    ulonglong2 wv = *(const ulonglong2*)(sm + OFF_WX + ((j) * 32 + lane) * 4); \
    u64t wy = *(const u64t*)(sm + OFF_WY + ((j) * 32 + lane) * 2); \
    ulonglong2 sa = LD2(SA + 32 + (j)); ulonglong2 sb = LD2(SB + 32 + (j)); \
    xA0 = f2_fma(wv.x, sa.x, xA0); xA1 = f2_fma(wv.x, sa.y, xA1); \
    xA2 = f2_fma(wv.x, sb.x, xA2); xA3 = f2_fma(wv.x, sb.y, xA3); \
    xB0 = f2_fma(wv.y, sa.x, xB0); xB1 = f2_fma(wv.y, sa.y, xB1); \
    xB2 = f2_fma(wv.y, sb.x, xB2); xB3 = f2_fma(wv.y, sb.y, xB3); \
    yv0 = f2_fma(wy, sa.x, yv0); yv1 = f2_fma(wy, sa.y, yv1); \
    yv2 = f2_fma(wy, sb.x, yv2); yv3 = f2_fma(wy, sb.y, yv3); }
#define CHAIN(i) { \
    float t0 = tanh_fast(a0), t1 = tanh_fast(a1), t2 = tanh_fast(a2), t3 = tanh_fast(a3); \
    t0 = __shfl_sync(0xffffffffu, t0, (i)); t1 = __shfl_sync(0xffffffffu, t1, (i)); \
    t2 = __shfl_sync(0xffffffffu, t2, (i)); t3 = __shfl_sync(0xffffffffu, t3, (i)); \
    float d = dc_r[i]; \
    a0 = fmaf(d, t0, a0); a1 = fmaf(d, t1, a1); \
    a2 = fmaf(d, t2, a2); a3 = fmaf(d, t3, a3); }

    for (int t = 0; t < T_STEPS; t++) {
        fS[idxu] = uc0; fS[idxu + 2] = uc1;
        fS[384 + idxu] = uc2; fS[384 + idxu + 2] = uc3;
        int tn = (t < T_STEPS - 1) ? (t + 1) : t;
        float un0 = up0[tn * 32 + lane], un1 = up1[tn * 32 + lane];
        float un2 = up2[tn * 32 + lane], un3 = up3[tn * 32 + lane];
        __syncwarp();

        // a-phase: j 0..15 u (kp 32..47), j 16..47 x (kp 64..95)
        u64t av0 = 0, av1 = 0, av2 = 0, av3 = 0;
        #pragma unroll
        for (int j = 0; j < 16; j++) MATA(32 + j, j);
        #pragma unroll
        for (int j = 16; j < 48; j++) MATA(48 + j, j);
        float a0 = f2_fold(av0), a1 = f2_fold(av1);
        float a2 = f2_fold(av2), a3 = f2_fold(av3);

        // chain + interleaved w-independent MATXY ops (48 ops: u j0..15, x j32..63)
        u64t xA0 = 0, xA1 = 0, xA2 = 0, xA3 = 0;
        u64t xB0 = 0, xB1 = 0, xB2 = 0, xB3 = 0;
        u64t yv0 = 0, yv1 = 0, yv2 = 0, yv3 = 0;
        #pragma unroll
        for (int i = 0; i < 16; i++) {
            CHAIN(i);
            { int m = 2 * i;     int op = (m < 16) ? m : m + 16; MATXY(op); }
            { int m = 2 * i + 1; int op = (m < 16) ? m : m + 16; MATXY(op); }
        }
        #pragma unroll
        for (int i = 16; i < 32; i++) { CHAIN(i); MATXY(i + 32); }

        // own w (a_lane final after iter=lane; later updates have zero coef)
        {
            float w0 = tanh_fast(a0), w1 = tanh_fast(a1);
            float w2 = tanh_fast(a2), w3 = tanh_fast(a3);
            fS[idxw] = w0; fS[idxw + 2] = w1;
            fS[384 + idxw] = w2; fS[384 + idxw + 2] = w3;
        }
        __syncwarp();

        // tail: w-part j16..31 (xn and y complete after this)
        #pragma unroll
        for (int j = 16; j < 32; j++) MATXY(j);
        fS[idxa] = f2_fold(xA0); fS[idxa + 2] = f2_fold(xA1);
        fS[384 + idxa] = f2_fold(xA2); fS[384 + idxa + 2] = f2_fold(xA3);
        fS[idxb] = f2_fold(xB0); fS[idxb + 2] = f2_fold(xB1);
        fS[384 + idxb] = f2_fold(xB2); fS[384 + idxb + 2] = f2_fold(xB3);
        yp0[t * 32] = f2_fold(yv0);
        yp1[t * 32] = f2_fold(yv1);
        yp2[t * 32] = f2_fold(yv2);
        yp3[t * 32] = f2_fold(yv3);

        uc0 = un0; uc1 = un1; uc2 = un2; uc3 = un3;
    }
}

// ---------------------------------------------------------------------------
extern "C" void kernel_launch(void* const* d_in, const int* in_sizes, int n_in,
                              void* d_out, int out_size) {
    const float* u_in  = (const float*)d_in[0];
    const float* x0    = (const float*)d_in[1];
    const float* X     = (const float*)d_in[2];
    const float* Y     = (const float*)d_in[3];
    const float* B2    = (const float*)d_in[4];
    const float* C2    = (const float*)d_in[5];
    const float* D12   = (const float*)d_in[6];
    const float* L     = (const float*)d_in[7];
    const float* U     = (const float*)d_in[8];
    const float* D21   = (const float*)d_in[9];
    const float* gamma = (const float*)d_in[10];
    float* y = (float*)d_out;

    const int setupa_smem  = 18464 * 4 + 256;              // 74112 B
    const int setupcd_smem = 64 * 128 * 4 + 64 * 4 + 256;  // 33280 B
    const int main_smem    = (16384 + 8 * 768) * 4;        // 90112 B

    cudaFuncSetAttribute(ren_setup_a,  cudaFuncAttributeMaxDynamicSharedMemorySize, setupa_smem);
    cudaFuncSetAttribute(ren_setup_cd, cudaFuncAttributeMaxDynamicSharedMemorySize, setupcd_smem);
    cudaFuncSetAttribute(ren_main,     cudaFuncAttributeMaxDynamicSharedMemorySize, main_smem);

    ren_setup_a<<<1, 256, setupa_smem>>>(B2, C2, D12, L, U, D21, gamma);
    ren_setup_b<<<160, 256>>>(X, C2, D21);
    ren_setup_cd<<<32, 512, setupcd_smem>>>(Y, B2, C2, D12, D21);
    ren_main<<<64, 256, main_smem>>>(u_in, x0, y);
}

// round 16
// speedup vs baseline: 1.3755x; 1.3755x over previous
#include <cuda_runtime.h>
#include <math.h>

#define T_STEPS 256
typedef unsigned long long u64t;

struct Sc {
    float D22[32 * 32];
    float vr[160 * 32];
    float T1[160 * 32];
    float H[160 * 160];
};
__device__ Sc g_s;

// Weight image: WA 3072 | WX 8192 | WYF 4096 | DC 1024 = 16384 floats (64 KB)
#define OFF_WA 0
#define OFF_WX 3072
#define OFF_WY 11264
#define OFF_DC 15360
__device__ __align__(16) float g_params[16384];

__device__ __forceinline__ u64t f2_fma(u64t a, u64t b, u64t c) {
    u64t d; asm("fma.rn.f32x2 %0,%1,%2,%3;" : "=l"(d) : "l"(a), "l"(b), "l"(c)); return d;
}
__device__ __forceinline__ float f2_fold(u64t v) {
    float lo, hi; asm("mov.b64 {%0,%1},%2;" : "=f"(lo), "=f"(hi) : "l"(v));
    return lo + hi;
}
// tanh via ex2+rcp (abs err ~1e-7)
__device__ __forceinline__ float tanh_fast(float x) {
    float t = x * 2.885390081777926814f;
    float e; asm("ex2.approx.f32 %0,%1;" : "=f"(e) : "f"(t));
    float r; asm("rcp.approx.f32 %0,%1;" : "=f"(r) : "f"(e + 1.0f));
    return fmaf(-2.0f, r, 1.0f);
}

// ---------------- Gauss-Jordan (fp32, warp-parallel partial pivot) ----------------
__device__ void gj_invert_f32(float* aug, int N, float* mv, int* s_piv, float* s_ipv) {
    const int tid = threadIdx.x, NT = blockDim.x;
    const int ld = 2 * N;
    for (int k = 0; k < N; k++) {
        if (tid < 32) {
            float best = -1.0f; int bi = k;
            for (int r = k + tid; r < N; r += 32) {
                float v = fabsf(aug[r * ld + k]);
                if (v > best) { best = v; bi = r; }
            }
            for (int o = 16; o; o >>= 1) {
                float ob = __shfl_down_sync(0xffffffffu, best, o);
                int   oi = __shfl_down_sync(0xffffffffu, bi, o);
                if (ob > best) { best = ob; bi = oi; }
            }
            if (tid == 0) *s_piv = bi;
        }
        __syncthreads();
        int p = *s_piv;
        if (p != k)
            for (int j = tid; j < ld; j += NT) {
                float tv = aug[k * ld + j];
                aug[k * ld + j] = aug[p * ld + j];
                aug[p * ld + j] = tv;
            }
        __syncthreads();
        if (tid == 0) *s_ipv = 1.0f / aug[k * ld + k];
        __syncthreads();
        float ipv = *s_ipv;
        for (int j = tid; j < ld; j += NT) aug[k * ld + j] *= ipv;
        __syncthreads();
        for (int r = tid; r < N; r += NT) mv[r] = aug[r * ld + k];
        __syncthreads();
        for (int idx = tid; idx < N * ld; idx += NT) {
            int r = idx / ld;
            if (r != k) {
                int j = idx - r * ld;
                aug[idx] -= mv[r] * aug[k * ld + j];
            }
        }
        __syncthreads();
    }
}

// ---------------- Setup A (1 block x 256) — ALL-SMEM ----------------
__global__ void ren_setup_a(const float* __restrict__ B2, const float* __restrict__ C2,
                            const float* __restrict__ D12, const float* __restrict__ L,
                            const float* __restrict__ U, const float* __restrict__ D21,
                            const float* __restrict__ gamma) {
    extern __shared__ float sf[];
    float* sL    = sf;
    float* sU    = sf + 1024;
    float* sC2   = sf + 2048;
    float* sD12  = sf + 4096;
    float* sD21  = sf + 5120;
    float* sB2   = sf + 6144;
    float* sD22  = sf + 8192;
    float* sM    = sf + 9216;
    float* aug   = sf + 10240;
    float* sRinv = sf + 12288;
    float* svr   = sf + 13312;
    float* mv    = sf + 18432;
    __shared__ int s_piv;
    __shared__ float s_ipv;
    const int tid = threadIdx.x, NT = blockDim.x;
    const float g = gamma[0];

    for (int i = tid; i < 1024; i += NT) sL[i]   = L[i];
    for (int i = tid; i < 1024; i += NT) sU[i]   = U[i];
    for (int i = tid; i < 2048; i += NT) sC2[i]  = C2[i];
    for (int i = tid; i < 1024; i += NT) sD12[i] = D12[i];
    for (int i = tid; i < 1024; i += NT) sD21[i] = D21[i];
    for (int i = tid; i < 2048; i += NT) sB2[i]  = B2[i];
    __syncthreads();

    for (int idx = tid; idx < 1024; idx += NT) {
        int i = idx >> 5, j = idx & 31;
        float acc = (i == j) ? (g + 1.0f) : 0.0f;
        #pragma unroll 8
        for (int k = 0; k < 32; k++) acc += sL[k * 32 + i] * sL[k * 32 + j];
        acc += sU[i * 32 + j] - sU[j * 32 + i];
        sD22[idx] = acc;
        g_s.D22[idx] = acc;
    }
    __syncthreads();

    for (int idx = tid; idx < 2048; idx += NT) {
        int i = idx >> 6, j = idx & 63;
        float v;
        if (j < 32) {
            float s = 0.0f;
            #pragma unroll 8
            for (int k = 0; k < 32; k++) s += sD22[k * 32 + i] * sD22[k * 32 + j];
            v = sD22[i * 32 + j] + sD22[j * 32 + i] - 1e-4f * s;
            if (i == j) v += -2.0f * g;
        } else v = ((j - 32) == i) ? 1.0f : 0.0f;
        aug[idx] = v;
    }
    __syncthreads();
    gj_invert_f32(aug, 32, mv, &s_piv, &s_ipv);
    for (int idx = tid; idx < 1024; idx += NT) {
        int i = idx >> 5, j = idx & 31;
        sRinv[idx] = aug[i * 64 + 32 + j];
    }
    for (int idx = tid; idx < 1024; idx += NT) {
        int i = idx >> 5, j = idx & 31;
        sM[idx] = ((i == j) ? 1.0f : 0.0f) - 1e-4f * sD22[j * 32 + i];
    }
    __syncthreads();

    for (int idx = tid; idx < 160 * 32; idx += NT) {
        int r = idx >> 5, c = idx & 31;
        float v;
        if (r < 64) {
            float s = 0.0f;
            #pragma unroll 8
            for (int k = 0; k < 32; k++) s += sM[c * 32 + k] * sC2[k * 64 + r];
            v = s;
        } else if (r < 96) {
            int rr = r - 64;
            float s = 0.0f;
            #pragma unroll 8
            for (int k = 0; k < 32; k++) s += sM[c * 32 + k] * sD21[k * 32 + rr];
            v = s - sD12[rr * 32 + c];
        } else v = sB2[(r - 96) * 32 + c];
        svr[idx] = v;
        g_s.vr[idx] = v;
    }
    __syncthreads();

    for (int idx = tid; idx < 160 * 32; idx += NT) {
        int r = idx >> 5, c = idx & 31;
        float s = 0.0f;
        #pragma unroll 8
        for (int k = 0; k < 32; k++) s += svr[r * 32 + k] * sRinv[k * 32 + c];
        g_s.T1[idx] = s;
    }
}

// ---------------- Setup B (160 blocks) ----------------
__global__ void ren_setup_b(const float* __restrict__ X, const float* __restrict__ C2,
                            const float* __restrict__ D21) {
    __shared__ float Xa[160];
    __shared__ float T1a[32];
    __shared__ float vqa[32];
    const int a = blockIdx.x;
    const int tid = threadIdx.x;
    for (int k = tid; k < 160; k += blockDim.x) Xa[k] = X[k * 160 + a];
    if (tid < 32) {
        T1a[tid] = g_s.T1[a * 32 + tid];
        float vq = 0.0f;
        if (a < 64) vq = C2[tid * 64 + a];
        else if (a < 96) vq = D21[tid * 32 + (a - 64)];
        vqa[tid] = vq;
    }
    __syncthreads();
    for (int b = tid; b < 160; b += blockDim.x) {
        float gsum = 0.0f;
        for (int k = 0; k < 160; k++) gsum += Xa[k] * X[k * 160 + b];
        float pr = 0.0f;
        for (int c = 0; c < 32; c++) pr += T1a[c] * g_s.vr[b * 32 + c];
        float q = 0.0f;
        if (b < 96)
            for (int c = 0; c < 32; c++) {
                float vb = (b < 64) ? C2[c * 64 + b] : D21[c * 32 + (b - 64)];
                q += vqa[c] * vb;
            }
        float h = gsum + pr + 1e-4f * q;
        if (a == b) h += 1e-3f;
        g_s.H[a * 160 + b] = h;
    }
}

// ---------------- Setup CD (32 blocks x 512) ----------------
__global__ void ren_setup_cd(const float* __restrict__ Y, const float* __restrict__ B2,
                             const float* __restrict__ C2, const float* __restrict__ D12,
                             const float* __restrict__ D21) {
    extern __shared__ float sf[];
    float* aug = sf;
    float* mv  = sf + 64 * 128;
    __shared__ int s_piv;
    __shared__ float s_ipv;
    __shared__ float CE[32 * 64];
    const int tid = threadIdx.x, NT = blockDim.x;

    for (int idx = tid; idx < 64 * 128; idx += NT) {
        int i = idx >> 7, j = idx & 127;
        float v;
        if (j < 64)
            v = 0.5f * (g_s.H[i * 160 + j] + g_s.H[(96 + i) * 160 + (96 + j)]
                        + Y[i * 64 + j] - Y[j * 64 + i]);
        else v = ((j - 64) == i) ? 1.0f : 0.0f;
        aug[idx] = v;
    }
    __syncthreads();
    gj_invert_f32(aug, 64, mv, &s_piv, &s_ipv);

#define EINV(r, c) (aug[(r) * 128 + 64 + (c)])
    for (int idx = tid; idx < 32 * 64; idx += NT) {
        int i = idx >> 6, n = idx & 63;
        float s = 0.0f;
        for (int m = 0; m < 64; m++) s += C2[i * 64 + m] * EINV(m, n);
        CE[idx] = s;
    }
    __syncthreads();

    const int g = blockIdx.x * 512 + tid;
    if (g < 8192) {
        int e = g;
        int comp = e & 3, r = e >> 2, j = r >> 5, lane = r & 31;
        int row = (comp < 2) ? lane : lane + 32;
        int c = comp & 1;
        float s = 0.0f;
        if (j < 16) {
            int col = 2 * j + c;
            for (int m = 0; m < 64; m++) s += EINV(row, m) * B2[m * 32 + col];
        } else if (j < 32) {
            int col = 2 * (j - 16) + c;
            for (int m = 0; m < 64; m++) s += EINV(row, m) * g_s.H[(96 + m) * 160 + 64 + col];
        } else {
            int col = 2 * (j - 32) + c;
            for (int m = 0; m < 64; m++) s += EINV(row, m) * g_s.H[(96 + m) * 160 + col];
        }
        g_params[OFF_WX + e] = s;
    } else if (g < 11264) {
        int e = g - 8192;
        int c = e & 1, r = e >> 1, j = r >> 5, i = r & 31;
        float invLam = 1.0f / (0.5f * g_s.H[(64 + i) * 160 + (64 + i)]);
        float v;
        if (j < 16) v = D12[i * 32 + 2 * j + c];
        else        v = -g_s.H[(64 + i) * 160 + 2 * (j - 16) + c];
        g_params[OFF_WA + e] = v * invLam;
    } else if (g < 15360) {
        int e = g - 11264;
        int c = e & 1, r = e >> 1, j = r >> 5, i = r & 31;
        int col;
        float val;
        if (j < 16)      { col = 2 * j + c;        val = g_s.D22[i * 32 + col]; }
        else if (j < 32) { col = 2 * (j - 16) + c; val = D21[i * 32 + col]; }
        else             { col = 2 * (j - 32) + c; val = 0.0f; }
        float acc = 0.0f;
        for (int n = 0; n < 64; n++) {
            float sv;
            if (j < 16)      sv = B2[n * 32 + col];
            else if (j < 32) sv = g_s.H[(96 + n) * 160 + 64 + col];
            else             sv = g_s.H[(96 + n) * 160 + col];
            acc += CE[i * 64 + n] * sv;
        }
        g_params[OFF_WY + e] = val + acc;
    } else {
        int e = g - 15360;
        int i = e >> 5, l = e & 31;
        float invLam = 1.0f / (0.5f * g_s.H[(64 + l) * 160 + (64 + l)]);
        g_params[OFF_DC + e] =
            (l > i) ? (-g_s.H[(64 + l) * 160 + (64 + i)] * invLam) : 0.0f;
    }
#undef EINV
}

// ---------------------------------------------------------------------------
// Main: R14 VERBATIM (measured 959 us): E=2, 8 warps/block (2/SMSP), 128
// blocks, y folded into x-phase (MATXY), wa_r + dc_r register-cached.
// ---------------------------------------------------------------------------
__global__ void __launch_bounds__(256, 1)
ren_main(const float* __restrict__ u_in, const float* __restrict__ x0,
         float* __restrict__ y_out) {
    extern __shared__ float sm[];
    {
        float4* dst = (float4*)sm;
        const float4* src = (const float4*)g_params;
        for (int i = threadIdx.x; i < 4096; i += blockDim.x) dst[i] = src[i];
    }
    const int warp = threadIdx.x >> 5;
    const int lane = threadIdx.x & 31;
    float* fS = sm + 16384 + warp * 384;
    const float4* SA = (const float4*)fS;
    __syncthreads();

    // register-cached weights
    u64t wa_r[48];
    #pragma unroll
    for (int j = 0; j < 48; j++)
        wa_r[j] = *(const u64t*)(sm + OFF_WA + (j * 32 + lane) * 2);
    float dc_r[32];
    #pragma unroll
    for (int i = 0; i < 32; i++)
        dc_r[i] = sm[OFF_DC + i * 32 + lane];

    const int e0 = (blockIdx.x * 8 + warp) * 2;
    const float* up0 = u_in + (size_t)(e0 + 0) * (T_STEPS * 32);
    const float* up1 = u_in + (size_t)(e0 + 1) * (T_STEPS * 32);
    float* yp0 = y_out + (size_t)(e0 + 0) * (T_STEPS * 32) + lane;
    float* yp1 = y_out + (size_t)(e0 + 1) * (T_STEPS * 32) + lane;

    // init x state (kp 64..95)
    {
        int ia = (64 + (lane >> 1)) * 4 + (lane & 1);
        int ib = (80 + (lane >> 1)) * 4 + (lane & 1);
        fS[ia]     = x0[(e0 + 0) * 64 + lane];
        fS[ia + 2] = x0[(e0 + 1) * 64 + lane];
        fS[ib]     = x0[(e0 + 0) * 64 + 32 + lane];
        fS[ib + 2] = x0[(e0 + 1) * 64 + 32 + lane];
    }
    float uc0 = up0[lane], uc1 = up1[lane];

    const int idxu = (32 + (lane >> 1)) * 4 + (lane & 1);
    const int idxw = (48 + (lane >> 1)) * 4 + (lane & 1);
    const int idxa = (64 + (lane >> 1)) * 4 + (lane & 1);
    const int idxb = (80 + (lane >> 1)) * 4 + (lane & 1);

#define LD2(p)  (*(const ulonglong2*)(p))
// a-phase state map: j<16 -> u at kp 32+j; j>=16 -> x at kp 48+j (=64..95)
#define MATA(kp, j) { \
    ulonglong2 s = LD2(SA + (kp)); \
    av0 = f2_fma(wa_r[j], s.x, av0); av1 = f2_fma(wa_r[j], s.y, av1); }
// combined x+y op: one state load feeds xn rowA, xn rowB, y row
#define MATXY(j) { \
    ulonglong2 wv = *(const ulonglong2*)(sm + OFF_WX + ((j) * 32 + lane) * 4); \
    u64t wy = *(const u64t*)(sm + OFF_WY + ((j) * 32 + lane) * 2); \
    ulonglong2 s  = LD2(SA + 32 + (j)); \
    xA0 = f2_fma(wv.x, s.x, xA0); xA1 = f2_fma(wv.x, s.y, xA1); \
    xB0 = f2_fma(wv.y, s.x, xB0); xB1 = f2_fma(wv.y, s.y, xB1); \
    yv0 = f2_fma(wy, s.x, yv0); yv1 = f2_fma(wy, s.y, yv1); }
#define CHAIN(i) { \
    float t0 = tanh_fast(a0), t1 = tanh_fast(a1); \
    t0 = __shfl_sync(0xffffffffu, t0, (i)); t1 = __shfl_sync(0xffffffffu, t1, (i)); \
    float d = dc_r[i]; \
    a0 = fmaf(d, t0, a0); a1 = fmaf(d, t1, a1); }

    for (int t = 0; t < T_STEPS; t++) {
        fS[idxu] = uc0; fS[idxu + 2] = uc1;
        int tn = (t < T_STEPS - 1) ? (t + 1) : t;
        float un0 = up0[tn * 32 + lane], un1 = up1[tn * 32 + lane];
        __syncwarp();

        // a-phase: j 0..15 u (kp 32..47), j 16..47 x (kp 64..95)
        u64t av0 = 0, av1 = 0;
        #pragma unroll
        for (int j = 0; j < 16; j++) MATA(32 + j, j);
        #pragma unroll
        for (int j = 16; j < 48; j++) MATA(48 + j, j);
        float a0 = f2_fold(av0), a1 = f2_fold(av1);

        // chain + interleaved w-independent MATXY ops
        u64t xA0 = 0, xA1 = 0, xB0 = 0, xB1 = 0;
        u64t yv0 = 0, yv1 = 0;
        #pragma unroll
        for (int i = 0; i < 16; i++) {
            CHAIN(i);
            { int m = 2 * i;     int op = (m < 16) ? m : m + 16; MATXY(op); }
            { int m = 2 * i + 1; int op = (m < 16) ? m : m + 16; MATXY(op); }
        }
        #pragma unroll
        for (int i = 16; i < 32; i++) { CHAIN(i); MATXY(i + 32); }

        // own w (a_lane final after iter=lane; later updates have zero coef)
        {
            float w0 = tanh_fast(a0), w1 = tanh_fast(a1);
            fS[idxw] = w0; fS[idxw + 2] = w1;
        }
        __syncwarp();

        // tail: w-part j16..31 (xn and y complete after this)
        #pragma unroll
        for (int j = 16; j < 32; j++) MATXY(j);
        fS[idxa] = f2_fold(xA0); fS[idxa + 2] = f2_fold(xA1);
        fS[idxb] = f2_fold(xB0); fS[idxb + 2] = f2_fold(xB1);
        yp0[t * 32] = f2_fold(yv0);
        yp1[t * 32] = f2_fold(yv1);

        uc0 = un0; uc1 = un1;
    }
}

// ---------------------------------------------------------------------------
extern "C" void kernel_launch(void* const* d_in, const int* in_sizes, int n_in,
                              void* d_out, int out_size) {
    const float* u_in  = (const float*)d_in[0];
    const float* x0    = (const float*)d_in[1];
    const float* X     = (const float*)d_in[2];
    const float* Y     = (const float*)d_in[3];
    const float* B2    = (const float*)d_in[4];
    const float* C2    = (const float*)d_in[5];
    const float* D12   = (const float*)d_in[6];
    const float* L     = (const float*)d_in[7];
    const float* U     = (const float*)d_in[8];
    const float* D21   = (const float*)d_in[9];
    const float* gamma = (const float*)d_in[10];
    float* y = (float*)d_out;

    const int setupa_smem  = 18464 * 4 + 256;              // 74112 B
    const int setupcd_smem = 64 * 128 * 4 + 64 * 4 + 256;  // 33280 B
    const int main_smem    = (16384 + 8 * 384) * 4;        // 77824 B

    cudaFuncSetAttribute(ren_setup_a,  cudaFuncAttributeMaxDynamicSharedMemorySize, setupa_smem);
    cudaFuncSetAttribute(ren_setup_cd, cudaFuncAttributeMaxDynamicSharedMemorySize, setupcd_smem);
    cudaFuncSetAttribute(ren_main,     cudaFuncAttributeMaxDynamicSharedMemorySize, main_smem);

    ren_setup_a<<<1, 256, setupa_smem>>>(B2, C2, D12, L, U, D21, gamma);
    ren_setup_b<<<160, 256>>>(X, C2, D21);
    ren_setup_cd<<<32, 512, setupcd_smem>>>(Y, B2, C2, D12, D21);
    ren_main<<<128, 256, main_smem>>>(u_in, x0, y);
}